// round 4
// baseline (speedup 1.0000x reference)
#include <cuda_runtime.h>

#define BATCH  2048
#define NPTS   4095
#define TPB    1024
#define NSUB   4          // sub-chunks per warp; warp segment = 128 elements

__device__ float g_partial[BATCH];
__device__ int   g_count = 0;

__global__ void __launch_bounds__(TPB)
mpd_fused_kernel(const float* __restrict__ o3,
                 const float* __restrict__ s3,
                 const float* __restrict__ o2,
                 const float* __restrict__ s2,
                 const float* __restrict__ df,
                 float* __restrict__ out)
{
    __shared__ float wtot[3][32];    // per-warp segment totals (x,y,z)
    __shared__ float red[32];
    __shared__ int   is_last;

    const int b = blockIdx.x;
    const int t = threadIdx.x;
    const unsigned lane = t & 31u;
    const unsigned warp = t >> 5;

    const float* __restrict__ s3b = s3 + (size_t)b * (3 * NPTS);
    const float* __restrict__ s2b = s2 + (size_t)b * (3 * NPTS);
    const float* __restrict__ dfb = df + (size_t)b * (2 * NPTS);

    const float dx = o3[b * 3 + 0] - o2[b * 3 + 0];
    const float dy = o3[b * 3 + 1] - o2[b * 3 + 1];
    const float dz = o3[b * 3 + 2] - o2[b * 3 + 2];

    // ---- Phase 1: compute v = shape3D - shape2D for this warp's 128-elem segment
    // element index: g = 128*warp + 32*c + lane  (each LDG: one 128B coalesced line)
    float vx[NSUB], vy[NSUB], vz[NSUB];
    #pragma unroll
    for (int c = 0; c < NSUB; c++) {
        const int g = (int)(warp << 7) + (c << 5) + (int)lane;
        const bool ok = (g < NPTS);            // only (warp31,c3,lane31) fails
        float r3  = ok ? s3b[g] : 0.f;
        float th3 = ok ? s3b[g + NPTS] : 0.f;
        float ph3 = ok ? s3b[g + 2 * NPTS] : 0.f;
        float r2  = ok ? s2b[g] : 0.f;
        float th2 = ok ? s2b[g + NPTS] : 0.f;
        float ph2 = ok ? s2b[g + 2 * NPTS] : 0.f;
        float dt  = ok ? dfb[g] : 0.f;
        float dp  = ok ? dfb[g + NPTS] : 0.f;

        float st, ct, sp, cp;
        __sincosf(th3 + dt, &st, &ct);
        __sincosf(ph3 + dp, &sp, &cp);
        float rst = r3 * st;
        float x = rst * cp, y = rst * sp, z = r3 * ct;
        __sincosf(th2, &st, &ct);
        __sincosf(ph2, &sp, &cp);
        rst = r2 * st;
        vx[c] = x - rst * cp;
        vy[c] = y - rst * sp;
        vz[c] = z - r2 * ct;
    }

    // ---- Phase 2: 12 independent intra-warp inclusive scans (no barriers)
    #pragma unroll
    for (int o = 1; o < 32; o <<= 1) {
        #pragma unroll
        for (int c = 0; c < NSUB; c++) {
            float ax = __shfl_up_sync(0xFFFFFFFFu, vx[c], o);
            float ay = __shfl_up_sync(0xFFFFFFFFu, vy[c], o);
            float az = __shfl_up_sync(0xFFFFFFFFu, vz[c], o);
            if (lane >= (unsigned)o) { vx[c] += ax; vy[c] += ay; vz[c] += az; }
        }
    }
    // lane 31 of v*[c] now holds the sub-chunk total

    // ---- Phase 3: warp segment totals -> smem, ONE barrier
    {
        float wx = 0.f, wy = 0.f, wz = 0.f;
        #pragma unroll
        for (int c = 0; c < NSUB; c++) {
            wx += __shfl_sync(0xFFFFFFFFu, vx[c], 31);
            wy += __shfl_sync(0xFFFFFFFFu, vy[c], 31);
            wz += __shfl_sync(0xFFFFFFFFu, vz[c], 31);
        }
        if (lane == 0) { wtot[0][warp] = wx; wtot[1][warp] = wy; wtot[2][warp] = wz; }
    }
    __syncthreads();

    // ---- Phase 4: every warp redundantly scans the 32 warp totals (registers)
    float px = wtot[0][lane], py = wtot[1][lane], pz = wtot[2][lane];
    #pragma unroll
    for (int o = 1; o < 32; o <<= 1) {
        float ax = __shfl_up_sync(0xFFFFFFFFu, px, o);
        float ay = __shfl_up_sync(0xFFFFFFFFu, py, o);
        float az = __shfl_up_sync(0xFFFFFFFFu, pz, o);
        if (lane >= (unsigned)o) { px += ax; py += ay; pz += az; }
    }
    // exclusive warp prefix for this warp = scanned value at lane warp-1 (0 if warp==0)
    const unsigned src = (warp == 0) ? 0u : (warp - 1u);
    float wpx = __shfl_sync(0xFFFFFFFFu, px, src);
    float wpy = __shfl_sync(0xFFFFFFFFu, py, src);
    float wpz = __shfl_sync(0xFFFFFFFFu, pz, src);
    float offx = dx + ((warp == 0) ? 0.f : wpx);
    float offy = dy + ((warp == 0) ? 0.f : wpy);
    float offz = dz + ((warp == 0) ? 0.f : wpz);

    // ---- Phase 5: abs-sum. sub-chunk offset advanced via lane-31 broadcasts
    float acc = 0.f;
    if (t == 0) acc = fabsf(dx) + fabsf(dy) + fabsf(dz);   // position 0 (origin)
    #pragma unroll
    for (int c = 0; c < NSUB; c++) {
        const int g = (int)(warp << 7) + (c << 5) + (int)lane;
        if (g < NPTS)
            acc += fabsf(offx + vx[c]) + fabsf(offy + vy[c]) + fabsf(offz + vz[c]);
        offx += __shfl_sync(0xFFFFFFFFu, vx[c], 31);
        offy += __shfl_sync(0xFFFFFFFFu, vy[c], 31);
        offz += __shfl_sync(0xFFFFFFFFu, vz[c], 31);
    }

    // ---- block reduce ----
    #pragma unroll
    for (int o = 16; o > 0; o >>= 1)
        acc += __shfl_down_sync(0xFFFFFFFFu, acc, o);
    if (lane == 0) red[warp] = acc;
    __syncthreads();
    if (warp == 0) {
        float a = red[lane];
        #pragma unroll
        for (int o = 16; o > 0; o >>= 1)
            a += __shfl_down_sync(0xFFFFFFFFu, a, o);
        if (lane == 0) g_partial[b] = a * (1.0f / (NPTS + 1));
    }

    // ---- fused deterministic final reduction in the last block ----
    if (t == 0) {
        __threadfence();
        int ticket = atomicAdd(&g_count, 1);
        is_last = (ticket == (int)gridDim.x - 1) ? 1 : 0;
    }
    __syncthreads();
    if (is_last) {
        float a = __ldcg(&g_partial[t]) + __ldcg(&g_partial[t + TPB]);
        #pragma unroll
        for (int o = 16; o > 0; o >>= 1)
            a += __shfl_down_sync(0xFFFFFFFFu, a, o);
        if (lane == 0) red[warp] = a;
        __syncthreads();
        if (warp == 0) {
            float v = red[lane];
            #pragma unroll
            for (int o = 16; o > 0; o >>= 1)
                v += __shfl_down_sync(0xFFFFFFFFu, v, o);
            if (lane == 0) {
                out[0] = v;
                atomicExch(&g_count, 0);   // reset for next graph replay
            }
        }
    }
}

extern "C" void kernel_launch(void* const* d_in, const int* in_sizes, int n_in,
                              void* d_out, int out_size)
{
    const float* o3 = (const float*)d_in[0];  // origin_3D        (B,3,1)
    const float* s3 = (const float*)d_in[1];  // spherical_3D     (B,3,N)
    const float* o2 = (const float*)d_in[2];  // origin_2D        (B,3,1)
    const float* s2 = (const float*)d_in[3];  // spherical_2D     (B,3,N)
    const float* df = (const float*)d_in[4];  // deformation_field(B,2,N)
    float* out = (float*)d_out;

    mpd_fused_kernel<<<BATCH, TPB>>>(o3, s3, o2, s2, df, out);
}

// round 5
// speedup vs baseline: 1.4898x; 1.4898x over previous
#include <cuda_runtime.h>

#define BATCH 2048
#define NPTS  4095
#define TPB   512
#define EPT   8       // TPB*EPT = 4096 >= NPTS
#define NWARP (TPB/32)
#define PADN  4096

__device__ float g_partial[BATCH];
__device__ int   g_count = 0;

// dynamic smem: ssx[4096] ssy[4096] ssz[4096]  (48 KB)
#define SMEM_BYTES (3 * PADN * 4)

extern __shared__ __align__(16) float sstage[];

__global__ void __launch_bounds__(TPB, 2)
mpd_fused_kernel(const float* __restrict__ o3,
                 const float* __restrict__ s3,
                 const float* __restrict__ o2,
                 const float* __restrict__ s2,
                 const float* __restrict__ df,
                 float* __restrict__ out)
{
    float* ssx = sstage;
    float* ssy = sstage + PADN;
    float* ssz = sstage + 2 * PADN;
    __shared__ float wsx[NWARP], wsy[NWARP], wsz[NWARP], red[NWARP];
    __shared__ int   is_last;

    const int b = blockIdx.x;
    const int t = threadIdx.x;
    const unsigned lane = t & 31u;
    const unsigned warp = t >> 5;

    const float* __restrict__ s3b = s3 + (size_t)b * (3 * NPTS);
    const float* __restrict__ s2b = s2 + (size_t)b * (3 * NPTS);
    const float* __restrict__ dfb = df + (size_t)b * (2 * NPTS);

    const float dx = o3[b * 3 + 0] - o2[b * 3 + 0];
    const float dy = o3[b * 3 + 1] - o2[b * 3 + 1];
    const float dz = o3[b * 3 + 2] - o2[b * 3 + 2];

    // ---- Phase A: cyclic (fully coalesced) loads + trig, staged to smem ----
    #pragma unroll
    for (int k = 0; k < EPT; k++) {
        const int i = t + k * TPB;           // lane stride 4B
        float vx = 0.f, vy = 0.f, vz = 0.f;
        if (i < NPTS) {                      // only the very last slot fails
            float r3  = s3b[i];
            float th3 = s3b[i + NPTS];
            float ph3 = s3b[i + 2 * NPTS];
            float r2  = s2b[i];
            float th2 = s2b[i + NPTS];
            float ph2 = s2b[i + 2 * NPTS];
            float dt  = dfb[i];
            float dp  = dfb[i + NPTS];

            float st, ct, sp, cp;
            __sincosf(th3 + dt, &st, &ct);
            __sincosf(ph3 + dp, &sp, &cp);
            float rst = r3 * st;
            vx = rst * cp; vy = rst * sp; vz = r3 * ct;
            __sincosf(th2, &st, &ct);
            __sincosf(ph2, &sp, &cp);
            rst = r2 * st;
            vx -= rst * cp; vy -= rst * sp; vz -= r2 * ct;
        }
        ssx[i] = vx; ssy[i] = vy; ssz[i] = vz;   // stride-1: conflict-free
    }
    __syncthreads();

    // ---- Phase B: blocked LDS.128 readback, thread-local scan of 8 ----
    const int base = t * EPT;                    // 32-byte aligned
    float4 X0 = *reinterpret_cast<const float4*>(ssx + base);
    float4 X1 = *reinterpret_cast<const float4*>(ssx + base + 4);
    float4 Y0 = *reinterpret_cast<const float4*>(ssy + base);
    float4 Y1 = *reinterpret_cast<const float4*>(ssy + base + 4);
    float4 Z0 = *reinterpret_cast<const float4*>(ssz + base);
    float4 Z1 = *reinterpret_cast<const float4*>(ssz + base + 4);

    float sx[EPT] = {X0.x, X0.y, X0.z, X0.w, X1.x, X1.y, X1.z, X1.w};
    float sy[EPT] = {Y0.x, Y0.y, Y0.z, Y0.w, Y1.x, Y1.y, Y1.z, Y1.w};
    float sz[EPT] = {Z0.x, Z0.y, Z0.z, Z0.w, Z1.x, Z1.y, Z1.z, Z1.w};

    #pragma unroll
    for (int k = 1; k < EPT; k++) {
        sx[k] += sx[k - 1];
        sy[k] += sy[k - 1];
        sz[k] += sz[k - 1];
    }
    const float tx = sx[EPT - 1], ty = sy[EPT - 1], tz = sz[EPT - 1];

    // warp inclusive scan of thread totals (the ONLY per-element-path shuffles)
    float ix = tx, iy = ty, iz = tz;
    #pragma unroll
    for (int o = 1; o < 32; o <<= 1) {
        float ax = __shfl_up_sync(0xFFFFFFFFu, ix, o);
        float ay = __shfl_up_sync(0xFFFFFFFFu, iy, o);
        float az = __shfl_up_sync(0xFFFFFFFFu, iz, o);
        if (lane >= (unsigned)o) { ix += ax; iy += ay; iz += az; }
    }

    // cross-warp scan (16 warps) via warp 0
    if (lane == 31) { wsx[warp] = ix; wsy[warp] = iy; wsz[warp] = iz; }
    __syncthreads();
    if (warp == 0) {
        float vx = (lane < NWARP) ? wsx[lane] : 0.f;
        float vy = (lane < NWARP) ? wsy[lane] : 0.f;
        float vz = (lane < NWARP) ? wsz[lane] : 0.f;
        #pragma unroll
        for (int o = 1; o < NWARP; o <<= 1) {
            float ax = __shfl_up_sync(0xFFFFFFFFu, vx, o);
            float ay = __shfl_up_sync(0xFFFFFFFFu, vy, o);
            float az = __shfl_up_sync(0xFFFFFFFFu, vz, o);
            if (lane >= (unsigned)o) { vx += ax; vy += ay; vz += az; }
        }
        if (lane < NWARP) { wsx[lane] = vx; wsy[lane] = vy; wsz[lane] = vz; }
    }
    __syncthreads();

    // exclusive offset for this thread
    float offx = dx + (ix - tx);
    float offy = dy + (iy - ty);
    float offz = dz + (iz - tz);
    if (warp > 0) {
        offx += wsx[warp - 1];
        offy += wsy[warp - 1];
        offz += wsz[warp - 1];
    }

    // abs-sum over this thread's 8 positions
    float acc = 0.f;
    if (t == 0) acc = fabsf(dx) + fabsf(dy) + fabsf(dz);   // j=0 (origin)
    #pragma unroll
    for (int k = 0; k < EPT; k++) {
        if (base + k < NPTS)
            acc += fabsf(offx + sx[k]) + fabsf(offy + sy[k]) + fabsf(offz + sz[k]);
    }

    // ---- block reduce ----
    #pragma unroll
    for (int o = 16; o > 0; o >>= 1)
        acc += __shfl_down_sync(0xFFFFFFFFu, acc, o);
    if (lane == 0) red[warp] = acc;
    __syncthreads();
    if (warp == 0) {
        float a = (lane < NWARP) ? red[lane] : 0.f;
        #pragma unroll
        for (int o = 16; o > 0; o >>= 1)
            a += __shfl_down_sync(0xFFFFFFFFu, a, o);
        if (lane == 0) g_partial[b] = a * (1.0f / (NPTS + 1));
    }

    // ---- fused deterministic final reduction in the last block ----
    if (t == 0) {
        __threadfence();
        int ticket = atomicAdd(&g_count, 1);
        is_last = (ticket == (int)gridDim.x - 1) ? 1 : 0;
    }
    __syncthreads();
    if (is_last) {
        float a = __ldcg(&g_partial[t])
                + __ldcg(&g_partial[t + TPB])
                + __ldcg(&g_partial[t + 2 * TPB])
                + __ldcg(&g_partial[t + 3 * TPB]);
        #pragma unroll
        for (int o = 16; o > 0; o >>= 1)
            a += __shfl_down_sync(0xFFFFFFFFu, a, o);
        if (lane == 0) red[warp] = a;
        __syncthreads();
        if (warp == 0) {
            float v = (lane < NWARP) ? red[lane] : 0.f;
            #pragma unroll
            for (int o = 16; o > 0; o >>= 1)
                v += __shfl_down_sync(0xFFFFFFFFu, v, o);
            if (lane == 0) {
                out[0] = v;
                atomicExch(&g_count, 0);   // reset for next graph replay
            }
        }
    }
}

extern "C" void kernel_launch(void* const* d_in, const int* in_sizes, int n_in,
                              void* d_out, int out_size)
{
    const float* o3 = (const float*)d_in[0];  // origin_3D        (B,3,1)
    const float* s3 = (const float*)d_in[1];  // spherical_3D     (B,3,N)
    const float* o2 = (const float*)d_in[2];  // origin_2D        (B,3,1)
    const float* s2 = (const float*)d_in[3];  // spherical_2D     (B,3,N)
    const float* df = (const float*)d_in[4];  // deformation_field(B,2,N)
    float* out = (float*)d_out;

    cudaFuncSetAttribute(mpd_fused_kernel,
                         cudaFuncAttributeMaxDynamicSharedMemorySize, SMEM_BYTES);
    mpd_fused_kernel<<<BATCH, TPB, SMEM_BYTES>>>(o3, s3, o2, s2, df, out);
}

// round 6
// speedup vs baseline: 1.5552x; 1.0439x over previous
#include <cuda_runtime.h>

#define BATCH 2048
#define NPTS  4095
#define TPB   512
#define HALF  2048          // elements per pass
#define LEPT  4             // TPB*LEPT = HALF
#define NPASS 2
#define NWARP (TPB/32)

__device__ float g_partial[BATCH];
__device__ int   g_count = 0;

// dynamic smem: ssx[2048] ssy[2048] ssz[2048]  (24 KB)
#define SMEM_BYTES (3 * HALF * 4)

extern __shared__ __align__(16) float sstage[];

__global__ void __launch_bounds__(TPB, 3)
mpd_fused_kernel(const float* __restrict__ o3,
                 const float* __restrict__ s3,
                 const float* __restrict__ o2,
                 const float* __restrict__ s2,
                 const float* __restrict__ df,
                 float* __restrict__ out)
{
    float* ssx = sstage;
    float* ssy = sstage + HALF;
    float* ssz = sstage + 2 * HALF;
    __shared__ float wsx[NWARP], wsy[NWARP], wsz[NWARP], red[NWARP];
    __shared__ int   is_last;

    const int b = blockIdx.x;
    const int t = threadIdx.x;
    const unsigned lane = t & 31u;
    const unsigned warp = t >> 5;

    const float* __restrict__ s3b = s3 + (size_t)b * (3 * NPTS);
    const float* __restrict__ s2b = s2 + (size_t)b * (3 * NPTS);
    const float* __restrict__ dfb = df + (size_t)b * (2 * NPTS);

    // running offset across passes; starts at origin delta
    float offx = o3[b * 3 + 0] - o2[b * 3 + 0];
    float offy = o3[b * 3 + 1] - o2[b * 3 + 1];
    float offz = o3[b * 3 + 2] - o2[b * 3 + 2];

    float acc = 0.f;
    if (t == 0) acc = fabsf(offx) + fabsf(offy) + fabsf(offz);  // j=0 (origin)

    #pragma unroll
    for (int p = 0; p < NPASS; p++) {
        const int pbase = p * HALF;

        // ---- Phase A: cyclic coalesced loads + trig, staged to smem ----
        #pragma unroll
        for (int k = 0; k < LEPT; k++) {
            const int il = t + k * TPB;          // 0..2047
            const int g  = pbase + il;
            float vx = 0.f, vy = 0.f, vz = 0.f;
            if (g < NPTS) {
                float r3  = s3b[g];
                float th3 = s3b[g + NPTS];
                float ph3 = s3b[g + 2 * NPTS];
                float r2  = s2b[g];
                float th2 = s2b[g + NPTS];
                float ph2 = s2b[g + 2 * NPTS];
                float dt  = dfb[g];
                float dp  = dfb[g + NPTS];

                float st, ct, sp, cp;
                __sincosf(th3 + dt, &st, &ct);
                __sincosf(ph3 + dp, &sp, &cp);
                float rst = r3 * st;
                vx = rst * cp; vy = rst * sp; vz = r3 * ct;
                __sincosf(th2, &st, &ct);
                __sincosf(ph2, &sp, &cp);
                rst = r2 * st;
                vx -= rst * cp; vy -= rst * sp; vz -= r2 * ct;
            }
            ssx[il] = vx; ssy[il] = vy; ssz[il] = vz;    // stride-1, conflict-free
        }
        __syncthreads();

        // ---- Phase B: blocked LDS.128 readback, local scan of 4 ----
        const int base = t * LEPT;                        // 16B aligned
        float4 X = *reinterpret_cast<const float4*>(ssx + base);
        float4 Y = *reinterpret_cast<const float4*>(ssy + base);
        float4 Z = *reinterpret_cast<const float4*>(ssz + base);

        float sx[LEPT] = {X.x, X.y, X.z, X.w};
        float sy[LEPT] = {Y.x, Y.y, Y.z, Y.w};
        float sz[LEPT] = {Z.x, Z.y, Z.z, Z.w};

        #pragma unroll
        for (int k = 1; k < LEPT; k++) {
            sx[k] += sx[k - 1];
            sy[k] += sy[k - 1];
            sz[k] += sz[k - 1];
        }
        const float tx = sx[LEPT - 1], ty = sy[LEPT - 1], tz = sz[LEPT - 1];

        // warp inclusive scan of thread totals
        float ix = tx, iy = ty, iz = tz;
        #pragma unroll
        for (int o = 1; o < 32; o <<= 1) {
            float ax = __shfl_up_sync(0xFFFFFFFFu, ix, o);
            float ay = __shfl_up_sync(0xFFFFFFFFu, iy, o);
            float az = __shfl_up_sync(0xFFFFFFFFu, iz, o);
            if (lane >= (unsigned)o) { ix += ax; iy += ay; iz += az; }
        }

        // cross-warp scan (16 warps) via warp 0
        if (lane == 31) { wsx[warp] = ix; wsy[warp] = iy; wsz[warp] = iz; }
        __syncthreads();
        if (warp == 0) {
            float vx = (lane < NWARP) ? wsx[lane] : 0.f;
            float vy = (lane < NWARP) ? wsy[lane] : 0.f;
            float vz = (lane < NWARP) ? wsz[lane] : 0.f;
            #pragma unroll
            for (int o = 1; o < NWARP; o <<= 1) {
                float ax = __shfl_up_sync(0xFFFFFFFFu, vx, o);
                float ay = __shfl_up_sync(0xFFFFFFFFu, vy, o);
                float az = __shfl_up_sync(0xFFFFFFFFu, vz, o);
                if (lane >= (unsigned)o) { vx += ax; vy += ay; vz += az; }
            }
            if (lane < NWARP) { wsx[lane] = vx; wsy[lane] = vy; wsz[lane] = vz; }
        }
        __syncthreads();

        // thread's exclusive prefix within this pass + running offset
        float ox = offx + (ix - tx);
        float oy = offy + (iy - ty);
        float oz = offz + (iz - tz);
        if (warp > 0) {
            ox += wsx[warp - 1];
            oy += wsy[warp - 1];
            oz += wsz[warp - 1];
        }

        // abs-sum over this thread's 4 positions
        #pragma unroll
        for (int k = 0; k < LEPT; k++) {
            if (pbase + base + k < NPTS)
                acc += fabsf(ox + sx[k]) + fabsf(oy + sy[k]) + fabsf(oz + sz[k]);
        }

        // advance running offset by this pass's block total
        offx += wsx[NWARP - 1];
        offy += wsy[NWARP - 1];
        offz += wsz[NWARP - 1];
        // (reads of ws* complete before next pass's writes: separated by
        //  the __syncthreads() after next Phase A)
    }

    // ---- block reduce of acc ----
    #pragma unroll
    for (int o = 16; o > 0; o >>= 1)
        acc += __shfl_down_sync(0xFFFFFFFFu, acc, o);
    if (lane == 0) red[warp] = acc;
    __syncthreads();
    if (warp == 0) {
        float a = (lane < NWARP) ? red[lane] : 0.f;
        #pragma unroll
        for (int o = 16; o > 0; o >>= 1)
            a += __shfl_down_sync(0xFFFFFFFFu, a, o);
        if (lane == 0) g_partial[b] = a * (1.0f / (NPTS + 1));
    }

    // ---- fused deterministic final reduction in the last block ----
    if (t == 0) {
        __threadfence();
        int ticket = atomicAdd(&g_count, 1);
        is_last = (ticket == (int)gridDim.x - 1) ? 1 : 0;
    }
    __syncthreads();
    if (is_last) {
        float a = __ldcg(&g_partial[t])
                + __ldcg(&g_partial[t + TPB])
                + __ldcg(&g_partial[t + 2 * TPB])
                + __ldcg(&g_partial[t + 3 * TPB]);
        #pragma unroll
        for (int o = 16; o > 0; o >>= 1)
            a += __shfl_down_sync(0xFFFFFFFFu, a, o);
        if (lane == 0) red[warp] = a;
        __syncthreads();
        if (warp == 0) {
            float v = (lane < NWARP) ? red[lane] : 0.f;
            #pragma unroll
            for (int o = 16; o > 0; o >>= 1)
                v += __shfl_down_sync(0xFFFFFFFFu, v, o);
            if (lane == 0) {
                out[0] = v;
                atomicExch(&g_count, 0);   // reset for next graph replay
            }
        }
    }
}

extern "C" void kernel_launch(void* const* d_in, const int* in_sizes, int n_in,
                              void* d_out, int out_size)
{
    const float* o3 = (const float*)d_in[0];  // origin_3D        (B,3,1)
    const float* s3 = (const float*)d_in[1];  // spherical_3D     (B,3,N)
    const float* o2 = (const float*)d_in[2];  // origin_2D        (B,3,1)
    const float* s2 = (const float*)d_in[3];  // spherical_2D     (B,3,N)
    const float* df = (const float*)d_in[4];  // deformation_field(B,2,N)
    float* out = (float*)d_out;

    cudaFuncSetAttribute(mpd_fused_kernel,
                         cudaFuncAttributeMaxDynamicSharedMemorySize, SMEM_BYTES);
    mpd_fused_kernel<<<BATCH, TPB, SMEM_BYTES>>>(o3, s3, o2, s2, df, out);
}